// round 7
// baseline (speedup 1.0000x reference)
#include <cuda_runtime.h>
#include <cuda_bf16.h>
#include <math.h>
#include <cstdint>

// Problem dims
#define TGT   64
#define SRC   64
#define BATCH 32
#define HID   512
#define ATT   512

// Scratch (no cudaMalloc allowed)
__device__ float g_hpart[TGT * BATCH * ATT];   // [t*BATCH+b][a]
__device__ float g_spart[SRC * BATCH * ATT];   // [s*BATCH+b][a]
__device__ float g_scores[TGT * BATCH * SRC];  // normalized attn: [(t*BATCH+b)*SRC + s]

// ---------------------------------------------------------------------------
// helpers
// ---------------------------------------------------------------------------
__device__ __forceinline__ float to_tf32(float x) {
    uint32_t u;
    asm("cvt.rna.tf32.f32 %0, %1;" : "=r"(u) : "f"(x));
    return __uint_as_float(u);
}
__device__ __forceinline__ float4 to_tf32_4(float4 v) {
    return make_float4(to_tf32(v.x), to_tf32(v.y), to_tf32(v.z), to_tf32(v.w));
}

__device__ __forceinline__ float tanh_fast(float x) {
    float y;
    asm("tanh.approx.f32 %0, %1;" : "=f"(y) : "f"(x));
    return y;
}

__device__ __forceinline__ void mma_tf32(float* c, const float* a, const float* b) {
    uint32_t a0 = __float_as_uint(a[0]), a1 = __float_as_uint(a[1]);
    uint32_t a2 = __float_as_uint(a[2]), a3 = __float_as_uint(a[3]);
    uint32_t b0 = __float_as_uint(b[0]), b1 = __float_as_uint(b[1]);
    asm volatile(
        "mma.sync.aligned.m16n8k8.row.col.f32.tf32.tf32.f32 "
        "{%0,%1,%2,%3}, {%4,%5,%6,%7}, {%8,%9}, {%0,%1,%2,%3};"
        : "+f"(c[0]), "+f"(c[1]), "+f"(c[2]), "+f"(c[3])
        : "r"(a0), "r"(a1), "r"(a2), "r"(a3), "r"(b0), "r"(b1));
}

// ---------------------------------------------------------------------------
// Kernel 1: tf32 mma.sync GEMM.  C[m][n] = sum_k A[m][k] * Wa_z[k][n]
// B read straight from Wa (row-major [k][n]) — no transpose kernel.
// 128x128 CTA tile, KT=32 double-buffered, one sync per stage.
// ---------------------------------------------------------------------------
#define KT     32
#define RSTR   36                    // A smem stride (floats)
#define BSTR   136                   // B smem stride (floats)
#define TILEA  (128 * RSTR)          // 4608 floats
#define TILEB  (KT * BSTR)           // 4352 floats

__global__ __launch_bounds__(256) void gemm_mma(
    const float* __restrict__ h_t,
    const float* __restrict__ src,
    const float* __restrict__ Wa)
{
    extern __shared__ __align__(16) float sm[];
    float* const Abuf[2] = { sm,             sm + TILEA };
    float* const Bbuf[2] = { sm + 2 * TILEA, sm + 2 * TILEA + TILEB };

    const int tid  = threadIdx.x;
    const int lane = tid & 31;
    const int wid  = tid >> 5;
    const int g    = lane >> 2;
    const int tg   = lane & 3;

    const int wm = (wid >> 1) * 32;
    const int wn = (wid & 1) * 64;

    const int ntile = blockIdx.x;
    const int mtile = blockIdx.y;
    const int z  = mtile >> 4;
    const float* A = (z == 0) ? h_t : src;
    const float* B = Wa + z * HID * ATT;         // [k][n]
    float*       C = (z == 0) ? g_hpart : g_spart;
    const int m0 = (mtile & 15) * 128;
    const int n0 = ntile * 128;

    // A staging indices: 1024 float4, row=idx>>3 (m), c4=idx&7 (k-quad)
    // B staging indices: 1024 float4, row=idx>>5 (k), c4=idx&31 (n-quad)

    float acc[2][8][4];
#pragma unroll
    for (int mi = 0; mi < 2; mi++)
#pragma unroll
        for (int ni = 0; ni < 8; ni++)
#pragma unroll
            for (int j = 0; j < 4; j++) acc[mi][ni][j] = 0.f;

    // ---- stage 0 ----
#pragma unroll
    for (int r = 0; r < 4; r++) {
        const int idx = r * 256 + tid;
        const int am  = idx >> 3, ak4 = idx & 7;
        float4 av = *(const float4*)(A + (m0 + am) * HID + ak4 * 4);
        *(float4*)(Abuf[0] + am * RSTR + ak4 * 4) = to_tf32_4(av);
        const int bk  = idx >> 5, bn4 = idx & 31;
        float4 bv = *(const float4*)(B + bk * ATT + n0 + bn4 * 4);
        *(float4*)(Bbuf[0] + bk * BSTR + bn4 * 4) = to_tf32_4(bv);
    }
    __syncthreads();

    for (int s = 0; s < 16; s++) {
        const int cur = s & 1;
        float4 ra[4], rb[4];
        if (s < 15) {
            const int kt = (s + 1) * KT;
#pragma unroll
            for (int r = 0; r < 4; r++) {
                const int idx = r * 256 + tid;
                const int am  = idx >> 3, ak4 = idx & 7;
                ra[r] = *(const float4*)(A + (m0 + am) * HID + kt + ak4 * 4);
                const int bk  = idx >> 5, bn4 = idx & 31;
                rb[r] = *(const float4*)(B + (kt + bk) * ATT + n0 + bn4 * 4);
            }
        }

        const float* Ab = Abuf[cur];
        const float* Bb = Bbuf[cur];
#pragma unroll
        for (int ks = 0; ks < 4; ks++) {
            const int k0 = ks * 8;
            float a[2][4];
#pragma unroll
            for (int mi = 0; mi < 2; mi++) {
                const float* ap = Ab + (wm + mi * 16 + g) * RSTR + k0 + tg;
                a[mi][0] = ap[0];
                a[mi][1] = ap[8 * RSTR];
                a[mi][2] = ap[4];
                a[mi][3] = ap[8 * RSTR + 4];
            }
            float b[8][2];
#pragma unroll
            for (int ni = 0; ni < 8; ni++) {
                const float* bp = Bb + (k0 + tg) * BSTR + wn + ni * 8 + g;
                b[ni][0] = bp[0];
                b[ni][1] = bp[4 * BSTR];
            }
#pragma unroll
            for (int mi = 0; mi < 2; mi++)
#pragma unroll
                for (int ni = 0; ni < 8; ni++)
                    mma_tf32(acc[mi][ni], a[mi], b[ni]);
        }

        if (s < 15) {
            const int nxt = cur ^ 1;
#pragma unroll
            for (int r = 0; r < 4; r++) {
                const int idx = r * 256 + tid;
                const int am  = idx >> 3, ak4 = idx & 7;
                *(float4*)(Abuf[nxt] + am * RSTR + ak4 * 4) = to_tf32_4(ra[r]);
                const int bk  = idx >> 5, bn4 = idx & 31;
                *(float4*)(Bbuf[nxt] + bk * BSTR + bn4 * 4) = to_tf32_4(rb[r]);
            }
            __syncthreads();
        }
    }

#pragma unroll
    for (int mi = 0; mi < 2; mi++) {
#pragma unroll
        for (int ni = 0; ni < 8; ni++) {
            const int row = m0 + wm + mi * 16 + g;
            const int col = n0 + wn + ni * 8 + 2 * tg;
            *(float2*)(C + row * ATT + col)       = make_float2(acc[mi][ni][0], acc[mi][ni][1]);
            *(float2*)(C + (row + 8) * ATT + col) = make_float2(acc[mi][ni][2], acc[mi][ni][3]);
        }
    }
}

// ---------------------------------------------------------------------------
// Kernel 2: fused scores + softmax.
// Block: one b, 8 t's, all 64 s. Thread pair (p, half) computes half the
// a-dim (256) for pair p = (ti, si); halves combined via shfl_xor(1).
// Warp w owns t = t0 + w (one t per warp) -> softmax fully in-warp.
// Writes normalized attn to g_scores.
// ---------------------------------------------------------------------------
#define SSTR 516

__global__ __launch_bounds__(256) void scores_softmax_kernel(
    const float* __restrict__ Va)
{
    extern __shared__ float smem[];
    float* hs = smem;                 // 8  * SSTR
    float* ss = smem + 8 * SSTR;      // 16 * SSTR
    float* va = smem + 24 * SSTR;     // 512

    const int b   = blockIdx.y;
    const int t0  = blockIdx.x * 8;
    const int tid = threadIdx.x;

    const int p    = tid >> 1;        // pair 0..127
    const int half = tid & 1;
    const int ti   = p >> 4;          // 0..7  (== warp id)
    const int si   = p & 15;          // 0..15
    const int aoff = half * 256;

    va[tid]       = Va[tid];
    va[tid + 256] = Va[tid + 256];

    // stage 8 h rows (1024 float4, 4/thread)
#pragma unroll
    for (int r = 0; r < 4; r++) {
        int idx  = r * 256 + tid;
        int row  = idx >> 7;          // 0..7
        int col4 = idx & 127;
        float4 v = *(const float4*)(g_hpart + ((t0 + row) * BATCH + b) * ATT + col4 * 4);
        *(float4*)(hs + row * SSTR + col4 * 4) = v;
    }

    float sc[4];

#pragma unroll
    for (int j = 0; j < 4; j++) {
        __syncthreads();   // prior chunk consumed (and hs staged on j=0)
        // stage 16 s rows (2048 float4, 8/thread)
#pragma unroll
        for (int r = 0; r < 8; r++) {
            int idx  = r * 256 + tid;
            int row  = idx >> 7;      // 0..15
            int col4 = idx & 127;
            float4 v = *(const float4*)(g_spart + ((j * 16 + row) * BATCH + b) * ATT + col4 * 4);
            *(float4*)(ss + row * SSTR + col4 * 4) = v;
        }
        __syncthreads();

        const float* hp = hs + ti * SSTR + aoff;
        const float* sp = ss + si * SSTR + aoff;
        const float* vp = va + aoff;
        float acc = 0.f;
#pragma unroll 4
        for (int a = 0; a < 256; a += 4) {
            float4 h4 = *(const float4*)(hp + a);
            float4 s4 = *(const float4*)(sp + a);
            float4 v4 = *(const float4*)(vp + a);
            acc = fmaf(tanh_fast(h4.x + s4.x), v4.x, acc);
            acc = fmaf(tanh_fast(h4.y + s4.y), v4.y, acc);
            acc = fmaf(tanh_fast(h4.z + s4.z), v4.z, acc);
            acc = fmaf(tanh_fast(h4.w + s4.w), v4.w, acc);
        }
        sc[j] = acc;
    }

    // combine a-halves: lanes differ in bit 0
#pragma unroll
    for (int j = 0; j < 4; j++)
        sc[j] += __shfl_xor_sync(0xffffffffu, sc[j], 1);

    // softmax over 64 s within the warp (reduce across si bits: lane bits 1-4)
    float mx = fmaxf(fmaxf(sc[0], sc[1]), fmaxf(sc[2], sc[3]));
#pragma unroll
    for (int o = 2; o <= 16; o <<= 1)
        mx = fmaxf(mx, __shfl_xor_sync(0xffffffffu, mx, o));

    float e[4], sum = 0.f;
#pragma unroll
    for (int j = 0; j < 4; j++) { e[j] = __expf(sc[j] - mx); sum += e[j]; }
#pragma unroll
    for (int o = 2; o <= 16; o <<= 1)
        sum += __shfl_xor_sync(0xffffffffu, sum, o);

    const float inv = 1.0f / sum;
    if (half == 0) {
        float* dst = g_scores + ((t0 + ti) * BATCH + b) * SRC;
#pragma unroll
        for (int j = 0; j < 4; j++)
            dst[j * 16 + si] = e[j] * inv;
    }
}

// ---------------------------------------------------------------------------
// Kernel 3: tensor-core context (attn already normalized in g_scores).
// Per block: one b, one 128-wide h-chunk. Register-prefetch attn + src,
// STS (tf32), one sync, mma (M=64 t, N=128 h, K=64 s). 128 blocks = 1 wave.
// ---------------------------------------------------------------------------
#define ASTR 68    // attn smem stride [t][s]
#define CSTR 132   // src chunk smem stride [s][h']

__global__ __launch_bounds__(256) void context_kernel(
    const float* __restrict__ src,
    float* __restrict__ out)
{
    extern __shared__ float dsm[];
    float* at = dsm;                 // attn [t][s]: 64*ASTR
    float* ss = dsm + 64 * ASTR;     // src chunk [s][h']: 64*CSTR

    const int b   = blockIdx.y;
    const int hc  = blockIdx.x;
    const int h0  = hc * 128;
    const int tid = threadIdx.x;
    const int wid  = tid >> 5;
    const int lane = tid & 31;

    // register prefetch: src (8 float4) + attn (4 float4), all independent LDGs
    float4 rs[8], ra[4];
#pragma unroll
    for (int r = 0; r < 8; r++) {
        const int idx = r * 256 + tid;        // 0..2047
        const int s   = idx >> 5;
        const int c4  = idx & 31;
        rs[r] = *(const float4*)(src + (s * BATCH + b) * HID + h0 + c4 * 4);
    }
#pragma unroll
    for (int r = 0; r < 4; r++) {
        const int idx = r * 256 + tid;        // 0..1023
        const int t   = idx >> 4;
        const int c4  = idx & 15;
        ra[r] = *(const float4*)(g_scores + (t * BATCH + b) * SRC + c4 * 4);
    }

#pragma unroll
    for (int r = 0; r < 8; r++) {
        const int idx = r * 256 + tid;
        const int s   = idx >> 5;
        const int c4  = idx & 31;
        *(float4*)(ss + s * CSTR + c4 * 4) = to_tf32_4(rs[r]);
    }
#pragma unroll
    for (int r = 0; r < 4; r++) {
        const int idx = r * 256 + tid;
        const int t   = idx >> 4;
        const int c4  = idx & 15;
        *(float4*)(at + t * ASTR + c4 * 4) = to_tf32_4(ra[r]);
    }
    __syncthreads();

    // mma: warp tile 16(t) x 64(h'), warps 4x2
    const int g  = lane >> 2;
    const int tg = lane & 3;
    const int wm = (wid & 3) * 16;
    const int wn = (wid >> 2) * 64;

    float acc[8][4];
#pragma unroll
    for (int ni = 0; ni < 8; ni++)
#pragma unroll
        for (int j = 0; j < 4; j++) acc[ni][j] = 0.f;

#pragma unroll
    for (int ks = 0; ks < 8; ks++) {
        const int k0 = ks * 8;
        float a[4];
        {
            const float* ap = at + (wm + g) * ASTR + k0 + tg;
            a[0] = ap[0];
            a[1] = ap[8 * ASTR];
            a[2] = ap[4];
            a[3] = ap[8 * ASTR + 4];
        }
        float bfr[8][2];
#pragma unroll
        for (int ni = 0; ni < 8; ni++) {
            const float* bp = ss + (k0 + tg) * CSTR + wn + ni * 8 + g;
            bfr[ni][0] = bp[0];
            bfr[ni][1] = bp[4 * CSTR];
        }
#pragma unroll
        for (int ni = 0; ni < 8; ni++)
            mma_tf32(acc[ni], a, bfr[ni]);
    }

#pragma unroll
    for (int ni = 0; ni < 8; ni++) {
        const int t   = wm + g;
        const int col = h0 + wn + ni * 8 + 2 * tg;
        *(float2*)(out + (t * BATCH + b) * HID + col)       = make_float2(acc[ni][0], acc[ni][1]);
        *(float2*)(out + ((t + 8) * BATCH + b) * HID + col) = make_float2(acc[ni][2], acc[ni][3]);
    }
}

// ---------------------------------------------------------------------------
extern "C" void kernel_launch(void* const* d_in, const int* in_sizes, int n_in,
                              void* d_out, int out_size)
{
    const float* h_t  = (const float*)d_in[0];   // (64, 32, 512)
    const float* srce = (const float*)d_in[1];   // (64, 32, 512)
    const float* Wa   = (const float*)d_in[2];   // (1024, 512)
    const float* Va   = (const float*)d_in[3];   // (512,)
    float* out = (float*)d_out;                  // (64, 32, 512)

    (void)in_sizes; (void)n_in; (void)out_size;

    // 1) tf32 mma GEMMs (B straight from Wa): grid (4 n, 32 m) = 128 CTAs
    const int gemm_smem = 2 * (TILEA + TILEB) * (int)sizeof(float);   // 71680 B
    cudaFuncSetAttribute(gemm_mma,
                         cudaFuncAttributeMaxDynamicSharedMemorySize, gemm_smem);
    gemm_mma<<<dim3(4, 32), 256, gemm_smem>>>(h_t, srce, Wa);

    // 2) fused scores + softmax: grid (8 t-tiles, 32 b) = 256 blocks, 2 CTA/SM
    const int sc_smem = (24 * SSTR + 512) * (int)sizeof(float);       // 51584 B
    cudaFuncSetAttribute(scores_softmax_kernel,
                         cudaFuncAttributeMaxDynamicSharedMemorySize, sc_smem);
    scores_softmax_kernel<<<dim3(8, 32), 256, sc_smem>>>(Va);

    // 3) mma context: grid (4 hc, 32 b) = 128 blocks
    const int ctx_smem = (64 * ASTR + 64 * CSTR) * (int)sizeof(float); // 51200 B
    cudaFuncSetAttribute(context_kernel,
                         cudaFuncAttributeMaxDynamicSharedMemorySize, ctx_smem);
    context_kernel<<<dim3(4, 32), 256, ctx_smem>>>(srce, out);
}

// round 8
// speedup vs baseline: 1.2118x; 1.2118x over previous
#include <cuda_runtime.h>
#include <cuda_bf16.h>
#include <math.h>
#include <cstdint>

// Problem dims
#define TGT   64
#define SRC   64
#define BATCH 32
#define HID   512
#define ATT   512

// Scratch (no cudaMalloc allowed)
__device__ float g_hpart[TGT * BATCH * ATT];   // [t*BATCH+b][a]
__device__ float g_spart[SRC * BATCH * ATT];   // [s*BATCH+b][a]
__device__ float g_scores[TGT * BATCH * SRC];  // [(t*BATCH+b)*SRC + s]
__device__ float g_A32[2 * TGT * BATCH * HID]; // tf32-rounded [h_t | src]
__device__ float g_B32[2 * HID * ATT];         // tf32-rounded Wa

// ---------------------------------------------------------------------------
// helpers
// ---------------------------------------------------------------------------
__device__ __forceinline__ float to_tf32(float x) {
    uint32_t u;
    asm("cvt.rna.tf32.f32 %0, %1;" : "=r"(u) : "f"(x));
    return __uint_as_float(u);
}
__device__ __forceinline__ float4 to_tf32_4(float4 v) {
    return make_float4(to_tf32(v.x), to_tf32(v.y), to_tf32(v.z), to_tf32(v.w));
}
__device__ __forceinline__ float tanh_fast(float x) {
    float y;
    asm("tanh.approx.f32 %0, %1;" : "=f"(y) : "f"(x));
    return y;
}
__device__ __forceinline__ uint32_t smem_u32(const void* p) {
    uint32_t a;
    asm("{ .reg .u64 t; cvta.to.shared.u64 t, %1; cvt.u32.u64 %0, t; }"
        : "=r"(a) : "l"(p));
    return a;
}
#define CP_ASYNC16(dst, srcp) \
    asm volatile("cp.async.cg.shared.global [%0], [%1], 16;" :: "r"(dst), "l"(srcp))
#define CP_COMMIT() asm volatile("cp.async.commit_group;" ::: "memory")
#define CP_WAIT1()  asm volatile("cp.async.wait_group 1;" ::: "memory")
#define CP_WAIT0()  asm volatile("cp.async.wait_group 0;" ::: "memory")

__device__ __forceinline__ void mma_tf32(float* c, const float* a, const float* b) {
    uint32_t a0 = __float_as_uint(a[0]), a1 = __float_as_uint(a[1]);
    uint32_t a2 = __float_as_uint(a[2]), a3 = __float_as_uint(a[3]);
    uint32_t b0 = __float_as_uint(b[0]), b1 = __float_as_uint(b[1]);
    asm volatile(
        "mma.sync.aligned.m16n8k8.row.col.f32.tf32.tf32.f32 "
        "{%0,%1,%2,%3}, {%4,%5,%6,%7}, {%8,%9}, {%0,%1,%2,%3};"
        : "+f"(c[0]), "+f"(c[1]), "+f"(c[2]), "+f"(c[3])
        : "r"(a0), "r"(a1), "r"(a2), "r"(a3), "r"(b0), "r"(b1));
}

// ---------------------------------------------------------------------------
// Kernel 0: round inputs to tf32 once. g_A32 = tf32([h_t | src]), g_B32 = tf32(Wa)
// ---------------------------------------------------------------------------
#define NA4 (2 * TGT * BATCH * HID / 4)   // 524288
#define NB4 (2 * HID * ATT / 4)           // 131072

__global__ __launch_bounds__(256) void round_inputs(
    const float* __restrict__ h_t,
    const float* __restrict__ src,
    const float* __restrict__ Wa)
{
    const int stride = gridDim.x * blockDim.x;
    for (int i = blockIdx.x * blockDim.x + threadIdx.x; i < NA4 + NB4; i += stride) {
        if (i < NA4 / 2) {
            ((float4*)g_A32)[i] = to_tf32_4(((const float4*)h_t)[i]);
        } else if (i < NA4) {
            ((float4*)g_A32)[i] = to_tf32_4(((const float4*)src)[i - NA4 / 2]);
        } else {
            ((float4*)g_B32)[i - NA4] = to_tf32_4(((const float4*)Wa)[i - NA4]);
        }
    }
}

// ---------------------------------------------------------------------------
// Kernel 1: tf32 mma GEMM, cp.async triple-buffered.
//   C[m][n] = sum_k A32[z][m][k] * B32[z*512+k][n]
// CTA tile 128(M) x 64(N), K in 16 stages of 32. Grid (8 n, 32 m) = 256 CTAs,
// 2 CTAs/SM. One __syncthreads per stage.
// ---------------------------------------------------------------------------
#define KT     32
#define ARS    36                     // A smem row stride (floats)
#define BRS    72                     // B smem row stride (floats)
#define STGF   (128 * ARS + KT * BRS) // floats per stage buffer (6912)

__global__ __launch_bounds__(256, 2) void gemm_mma(void)
{
    extern __shared__ __align__(16) float sm[];
    const uint32_t smb = smem_u32(sm);

    const int tid  = threadIdx.x;
    const int lane = tid & 31;
    const int wid  = tid >> 5;
    const int g    = lane >> 2;
    const int tg   = lane & 3;

    const int wm = (wid >> 1) * 32;    // 0,32,64,96
    const int wn = (wid & 1) * 32;     // 0,32

    const int ntile = blockIdx.x;      // 0..7
    const int mtile = blockIdx.y;      // 0..31
    const int z  = mtile >> 4;
    const int m0 = (mtile & 15) * 128;
    const int n0 = ntile * 64;
    const float* A = g_A32 + z * (TGT * BATCH * HID);
    const float* B = g_B32 + z * (HID * ATT);
    float*       C = (z == 0) ? g_hpart : g_spart;

    // staging: A 1024 16B-chunks (4/thread), B 512 chunks (2/thread)
    const int aam  = tid >> 1;             // with r offset: am = (r*256+tid)>>3
    (void)aam;

    // stage function via macro-ish lambda
    auto stage = [&](int s, int bufi) {
        const int kt = s * KT;
        const uint32_t bufA = smb + (uint32_t)(bufi * STGF) * 4u;
        const uint32_t bufB = bufA + 128u * ARS * 4u;
#pragma unroll
        for (int r = 0; r < 4; r++) {
            const int idx = r * 256 + tid;       // 0..1023
            const int am  = idx >> 3, ak4 = idx & 7;
            CP_ASYNC16(bufA + (uint32_t)(am * ARS + ak4 * 4) * 4u,
                       A + (m0 + am) * HID + kt + ak4 * 4);
        }
#pragma unroll
        for (int r = 0; r < 2; r++) {
            const int idx = r * 256 + tid;       // 0..511
            const int bk  = idx >> 4, bn4 = idx & 15;
            CP_ASYNC16(bufB + (uint32_t)(bk * BRS + bn4 * 4) * 4u,
                       B + (kt + bk) * ATT + n0 + bn4 * 4);
        }
    };

    float acc[2][4][4];
#pragma unroll
    for (int mi = 0; mi < 2; mi++)
#pragma unroll
        for (int ni = 0; ni < 4; ni++)
#pragma unroll
            for (int j = 0; j < 4; j++) acc[mi][ni][j] = 0.f;

    stage(0, 0); CP_COMMIT();
    stage(1, 1); CP_COMMIT();

    for (int s = 0; s < 16; s++) {
        if (s < 15) CP_WAIT1(); else CP_WAIT0();
        __syncthreads();
        if (s + 2 < 16) { stage(s + 2, (s + 2) % 3); CP_COMMIT(); }

        const float* Ab = sm + (s % 3) * STGF;
        const float* Bb = Ab + 128 * ARS;
#pragma unroll
        for (int ks = 0; ks < 4; ks++) {
            const int k0 = ks * 8;
            float a[2][4];
#pragma unroll
            for (int mi = 0; mi < 2; mi++) {
                const float* ap = Ab + (wm + mi * 16 + g) * ARS + k0 + tg;
                a[mi][0] = ap[0];
                a[mi][1] = ap[8 * ARS];
                a[mi][2] = ap[4];
                a[mi][3] = ap[8 * ARS + 4];
            }
            float b[4][2];
#pragma unroll
            for (int ni = 0; ni < 4; ni++) {
                const float* bp = Bb + (k0 + tg) * BRS + wn + ni * 8 + g;
                b[ni][0] = bp[0];
                b[ni][1] = bp[4 * BRS];
            }
#pragma unroll
            for (int mi = 0; mi < 2; mi++)
#pragma unroll
                for (int ni = 0; ni < 4; ni++)
                    mma_tf32(acc[mi][ni], a[mi], b[ni]);
        }
    }

#pragma unroll
    for (int mi = 0; mi < 2; mi++) {
#pragma unroll
        for (int ni = 0; ni < 4; ni++) {
            const int row = m0 + wm + mi * 16 + g;
            const int col = n0 + wn + ni * 8 + 2 * tg;
            *(float2*)(C + row * ATT + col)       = make_float2(acc[mi][ni][0], acc[mi][ni][1]);
            *(float2*)(C + (row + 8) * ATT + col) = make_float2(acc[mi][ni][2], acc[mi][ni][3]);
        }
    }
}

// ---------------------------------------------------------------------------
// Kernel 2: scores[s,t,b] = sum_a tanh(h_part[t,b,a] + s_part[s,b,a]) * Va[a]
// (R6 version — MUFU.TANH floor)
// ---------------------------------------------------------------------------
#define SSTR 516

__global__ __launch_bounds__(256) void scores_kernel(
    const float* __restrict__ Va)
{
    extern __shared__ float smem[];
    float* hs = smem;                 // 16 * SSTR
    float* ss = smem + 16 * SSTR;     // 16 * SSTR
    float* va = smem + 32 * SSTR;     // 512

    const int b     = blockIdx.z;
    const int t0    = blockIdx.y * 16;
    const int sbase = blockIdx.x * 32;
    const int tid   = threadIdx.x;

    va[tid]       = Va[tid];
    va[tid + 256] = Va[tid + 256];

#pragma unroll
    for (int r = 0; r < 8; r++) {
        int idx  = r * 256 + tid;
        int row  = idx >> 7;
        int col4 = idx & 127;
        float4 v = *(const float4*)(g_hpart + ((t0 + row) * BATCH + b) * ATT + col4 * 4);
        *(float4*)(hs + row * SSTR + col4 * 4) = v;
    }

    const int si = tid & 15;
    const int ti = tid >> 4;

    for (int sc = 0; sc < 32; sc += 16) {
        __syncthreads();
#pragma unroll
        for (int r = 0; r < 8; r++) {
            int idx  = r * 256 + tid;
            int row  = idx >> 7;
            int col4 = idx & 127;
            float4 v = *(const float4*)(g_spart + ((sbase + sc + row) * BATCH + b) * ATT + col4 * 4);
            *(float4*)(ss + row * SSTR + col4 * 4) = v;
        }
        __syncthreads();

        const float* hp = hs + ti * SSTR;
        const float* sp = ss + si * SSTR;
        float acc = 0.f;
#pragma unroll 4
        for (int a = 0; a < 512; a += 4) {
            float4 h4 = *(const float4*)(hp + a);
            float4 s4 = *(const float4*)(sp + a);
            float4 v4 = *(const float4*)(va + a);
            acc = fmaf(tanh_fast(h4.x + s4.x), v4.x, acc);
            acc = fmaf(tanh_fast(h4.y + s4.y), v4.y, acc);
            acc = fmaf(tanh_fast(h4.z + s4.z), v4.z, acc);
            acc = fmaf(tanh_fast(h4.w + s4.w), v4.w, acc);
        }
        const int s = sbase + sc + si;
        const int t = t0 + ti;
        g_scores[(t * BATCH + b) * SRC + s] = acc;
    }
}

// ---------------------------------------------------------------------------
// Kernel 3: fused softmax + tensor-core context. (R6 version)
// ---------------------------------------------------------------------------
#define ASTR 68
#define CSTR 132

__global__ __launch_bounds__(256) void softmax_context_kernel(
    const float* __restrict__ src,
    float* __restrict__ out)
{
    extern __shared__ float dsm[];
    float* at = dsm;                 // attn^T [t][s]: 64*ASTR
    float* ss = dsm + 64 * ASTR;     // src chunk [s][h']: 64*CSTR

    const int b   = blockIdx.y;
    const int hc  = blockIdx.x;
    const int h0  = hc * 128;
    const int tid = threadIdx.x;
    const int wid  = tid >> 5;
    const int lane = tid & 31;

#pragma unroll
    for (int r = 0; r < 8; r++) {
        const int t = wid * 8 + r;
        const float* srow = g_scores + (t * BATCH + b) * SRC;
        float v0 = srow[lane];
        float v1 = srow[lane + 32];
        float mx = fmaxf(v0, v1);
#pragma unroll
        for (int o = 16; o > 0; o >>= 1)
            mx = fmaxf(mx, __shfl_xor_sync(0xffffffffu, mx, o));
        float e0 = __expf(v0 - mx);
        float e1 = __expf(v1 - mx);
        float sum = e0 + e1;
#pragma unroll
        for (int o = 16; o > 0; o >>= 1)
            sum += __shfl_xor_sync(0xffffffffu, sum, o);
        float inv = 1.0f / sum;
        at[t * ASTR + lane]      = to_tf32(e0 * inv);
        at[t * ASTR + lane + 32] = to_tf32(e1 * inv);
    }

#pragma unroll
    for (int r = 0; r < 8; r++) {
        const int idx = r * 256 + tid;
        const int s   = idx >> 5;
        const int c4  = idx & 31;
        float4 v = *(const float4*)(src + (s * BATCH + b) * HID + h0 + c4 * 4);
        *(float4*)(ss + s * CSTR + c4 * 4) = to_tf32_4(v);
    }
    __syncthreads();

    const int g  = lane >> 2;
    const int tg = lane & 3;
    const int wm = (wid & 3) * 16;
    const int wn = (wid >> 2) * 64;

    float acc[8][4];
#pragma unroll
    for (int ni = 0; ni < 8; ni++)
#pragma unroll
        for (int j = 0; j < 4; j++) acc[ni][j] = 0.f;

#pragma unroll
    for (int ks = 0; ks < 8; ks++) {
        const int k0 = ks * 8;
        float a[4];
        {
            const float* ap = at + (wm + g) * ASTR + k0 + tg;
            a[0] = ap[0];
            a[1] = ap[8 * ASTR];
            a[2] = ap[4];
            a[3] = ap[8 * ASTR + 4];
        }
        float bfr[8][2];
#pragma unroll
        for (int ni = 0; ni < 8; ni++) {
            const float* bp = ss + (k0 + tg) * CSTR + wn + ni * 8 + g;
            bfr[ni][0] = bp[0];
            bfr[ni][1] = bp[4 * CSTR];
        }
#pragma unroll
        for (int ni = 0; ni < 8; ni++)
            mma_tf32(acc[ni], a, bfr[ni]);
    }

#pragma unroll
    for (int ni = 0; ni < 8; ni++) {
        const int t   = wm + g;
        const int col = h0 + wn + ni * 8 + 2 * tg;
        *(float2*)(out + (t * BATCH + b) * HID + col)       = make_float2(acc[ni][0], acc[ni][1]);
        *(float2*)(out + ((t + 8) * BATCH + b) * HID + col) = make_float2(acc[ni][2], acc[ni][3]);
    }
}

// ---------------------------------------------------------------------------
extern "C" void kernel_launch(void* const* d_in, const int* in_sizes, int n_in,
                              void* d_out, int out_size)
{
    const float* h_t  = (const float*)d_in[0];   // (64, 32, 512)
    const float* srce = (const float*)d_in[1];   // (64, 32, 512)
    const float* Wa   = (const float*)d_in[2];   // (1024, 512)
    const float* Va   = (const float*)d_in[3];   // (512,)
    float* out = (float*)d_out;                  // (64, 32, 512)

    (void)in_sizes; (void)n_in; (void)out_size;

    // 0) tf32 pre-round
    round_inputs<<<256, 256>>>(h_t, srce, Wa);

    // 1) GEMMs: grid (8 n, 32 m) = 256 CTAs, 2/SM, cp.async triple buffer
    const int gemm_smem = 3 * STGF * (int)sizeof(float);   // 82944 B
    cudaFuncSetAttribute(gemm_mma,
                         cudaFuncAttributeMaxDynamicSharedMemorySize, gemm_smem);
    gemm_mma<<<dim3(8, 32), 256, gemm_smem>>>();

    // 2) scores: grid (s-halves=2, t-tiles=4, b=32)
    const int sc_smem = (32 * SSTR + 512) * (int)sizeof(float);
    cudaFuncSetAttribute(scores_kernel,
                         cudaFuncAttributeMaxDynamicSharedMemorySize, sc_smem);
    scores_kernel<<<dim3(2, 4, 32), 256, sc_smem>>>(Va);

    // 3) fused softmax + mma context: grid (4 hc, 32 b) = 128 blocks
    const int ctx_smem = (64 * ASTR + 64 * CSTR) * (int)sizeof(float);
    cudaFuncSetAttribute(softmax_context_kernel,
                         cudaFuncAttributeMaxDynamicSharedMemorySize, ctx_smem);
    softmax_context_kernel<<<dim3(4, 32), 256, ctx_smem>>>(srce, out);
}